// round 1
// baseline (speedup 1.0000x reference)
#include <cuda_runtime.h>
#include <math.h>

#define BATCH 8192

// Scratch (device globals; no allocation allowed)
__device__ float g_a1[BATCH * 16 * 14 * 14];  // pool1 out
__device__ float g_a2[BATCH * 32 * 7 * 7];    // pool2 out
__device__ float g_a3[BATCH * 1024];          // pool3 out (flattened)
__device__ float g_a4[BATCH * 256];           // fc1 out

// ---------------- conv1 (1->16, 5x5, pad2) + relu + maxpool2 ----------------
// One block per image. Thread = one pooled (py,px), all 16 oc jointly.
__global__ void __launch_bounds__(224) k_conv1(const float* __restrict__ x,
                                               const float* __restrict__ w1,
                                               const float* __restrict__ b1) {
    __shared__ float s_in[32 * 33];  // padded 32 rows, stride 33 (odd)
    __shared__ float s_w[400];
    __shared__ float s_b[16];
    const int img = blockIdx.x;
    const int tid = threadIdx.x;

    for (int i = tid; i < 32 * 33; i += 224) s_in[i] = 0.f;
    for (int i = tid; i < 400; i += 224) s_w[i] = w1[i];
    if (tid < 16) s_b[tid] = b1[tid];
    __syncthreads();
    const float* xin = x + img * 784;
    for (int i = tid; i < 784; i += 224) {
        int r = i / 28, c = i - r * 28;
        s_in[(r + 2) * 33 + (c + 2)] = xin[i];
    }
    __syncthreads();

    if (tid < 196) {
        int py = tid / 14, px = tid - py * 14;
        int y0 = 2 * py, x0 = 2 * px;
        float acc[16][4];
#pragma unroll
        for (int j = 0; j < 16; j++) {
            float bv = s_b[j];
            acc[j][0] = bv; acc[j][1] = bv; acc[j][2] = bv; acc[j][3] = bv;
        }
#pragma unroll
        for (int ky = 0; ky < 5; ky++) {
            const float* r0 = &s_in[(y0 + ky) * 33 + x0];
            const float* r1 = r0 + 33;
#pragma unroll
            for (int kx = 0; kx < 5; kx++) {
                float i0 = r0[kx], i1 = r0[kx + 1], i2 = r1[kx], i3 = r1[kx + 1];
#pragma unroll
                for (int j = 0; j < 16; j++) {
                    float wv = s_w[j * 25 + ky * 5 + kx];
                    acc[j][0] += wv * i0; acc[j][1] += wv * i1;
                    acc[j][2] += wv * i2; acc[j][3] += wv * i3;
                }
            }
        }
        float* o = g_a1 + img * 3136 + py * 14 + px;
#pragma unroll
        for (int j = 0; j < 16; j++) {
            float m = fmaxf(fmaxf(acc[j][0], acc[j][1]), fmaxf(acc[j][2], acc[j][3]));
            o[j * 196] = fmaxf(m, 0.f);
        }
    }
}

// ---------------- conv2 (16->32, 5x5, pad2) + relu + maxpool2 ----------------
// One block per image. Thread = one pooled (py,px), 8 oc jointly (ocq selects group).
__global__ void __launch_bounds__(224) k_conv2(const float* __restrict__ w2,
                                               const float* __restrict__ b2) {
    extern __shared__ float sm2[];
    float* s_in = sm2;             // 16 * 18 * 19 = 5472
    float* s_w  = sm2 + 5472;      // 12800
    float* s_b  = s_w + 12800;     // 32
    const int img = blockIdx.x;
    const int tid = threadIdx.x;

    for (int i = tid; i < 5472; i += 224) s_in[i] = 0.f;
    for (int i = tid; i < 12800; i += 224) s_w[i] = w2[i];
    if (tid < 32) s_b[tid] = b2[tid];
    __syncthreads();
    const float* ain = g_a1 + img * 3136;
    for (int i = tid; i < 3136; i += 224) {
        int ic = i / 196; int rem = i - ic * 196;
        int r = rem / 14, c = rem - r * 14;
        s_in[ic * 342 + (r + 2) * 19 + (c + 2)] = ain[i];
    }
    __syncthreads();

    if (tid < 196) {
        int ocq = tid / 49; int sp = tid - ocq * 49;
        int py = sp / 7, px = sp - py * 7;
        int y0 = 2 * py, x0 = 2 * px;
        float acc[8][4];
#pragma unroll
        for (int j = 0; j < 8; j++) {
            float bv = s_b[ocq * 8 + j];
            acc[j][0] = bv; acc[j][1] = bv; acc[j][2] = bv; acc[j][3] = bv;
        }
        const float* wb = s_w + ocq * 8 * 400;
        for (int ic = 0; ic < 16; ic++) {
            const float* pin = s_in + ic * 342 + y0 * 19 + x0;
            const float* pw  = wb + ic * 25;
#pragma unroll
            for (int ky = 0; ky < 5; ky++) {
                const float* r0 = pin + ky * 19;
                const float* r1 = r0 + 19;
#pragma unroll
                for (int kx = 0; kx < 5; kx++) {
                    float i0 = r0[kx], i1 = r0[kx + 1], i2 = r1[kx], i3 = r1[kx + 1];
#pragma unroll
                    for (int j = 0; j < 8; j++) {
                        float wv = pw[j * 400 + ky * 5 + kx];
                        acc[j][0] += wv * i0; acc[j][1] += wv * i1;
                        acc[j][2] += wv * i2; acc[j][3] += wv * i3;
                    }
                }
            }
        }
        float* o = g_a2 + img * 1568 + (ocq * 8) * 49 + sp;
#pragma unroll
        for (int j = 0; j < 8; j++) {
            float m = fmaxf(fmaxf(acc[j][0], acc[j][1]), fmaxf(acc[j][2], acc[j][3]));
            o[j * 49] = fmaxf(m, 0.f);
        }
    }
}

// ------------- conv3 (32->64, 5x5, pad2) + relu + maxpool2(pad1) -------------
// Block = 4 images x 16-oc group. Thread = (imgl, ocq of 4 oc, pooled sp of 16).
__global__ void __launch_bounds__(256) k_conv3(const float* __restrict__ w3,
                                               const float* __restrict__ b3) {
    extern __shared__ float sm3[];
    float* s_in = sm3;             // 4 * 32 * 11 * 13 = 18304
    float* s_w  = sm3 + 18304;     // 16 * 800 = 12800
    float* s_b  = s_w + 12800;     // 16
    const int img0 = blockIdx.x * 4;
    const int ocg  = blockIdx.y;   // 0..3 -> 16 oc each
    const int tid  = threadIdx.x;

    for (int i = tid; i < 18304; i += 256) s_in[i] = 0.f;
    const float* wg = w3 + ocg * 16 * 800;
    for (int i = tid; i < 12800; i += 256) s_w[i] = wg[i];
    if (tid < 16) s_b[tid] = b3[ocg * 16 + tid];
    __syncthreads();
    for (int i = tid; i < 4 * 1568; i += 256) {
        int imgl = i / 1568; int rem = i - imgl * 1568;
        int ic = rem / 49; int r2 = rem - ic * 49;
        int r = r2 / 7, c = r2 - r * 7;
        s_in[imgl * 4576 + ic * 143 + (r + 2) * 13 + (c + 2)] =
            g_a2[(img0 + imgl) * 1568 + rem];
    }
    __syncthreads();

    const int imgl = tid >> 6;
    const int ocq  = (tid >> 4) & 3;
    const int sp   = tid & 15;
    const int py = sp >> 2, px = sp & 3;
    // pool window (pad=1, -inf): conv rows {2py-1, 2py}, cols {2px-1, 2px}
    const int cy1 = 2 * py, cx1 = 2 * px;
    const bool vy = (py > 0), vx = (px > 0);
    const int cy0c = vy ? (cy1 - 1) : 0;
    const int cx0c = vx ? (cx1 - 1) : 0;

    float acc[4][4];
#pragma unroll
    for (int j = 0; j < 4; j++) {
        float bv = s_b[ocq * 4 + j];
        acc[j][0] = bv; acc[j][1] = bv; acc[j][2] = bv; acc[j][3] = bv;
    }
    const float* base_in = s_in + imgl * 4576;
    const float* wb = s_w + ocq * 4 * 800;
    for (int ic = 0; ic < 32; ic++) {
        const float* pin = base_in + ic * 143;
        const float* pw  = wb + ic * 25;
#pragma unroll
        for (int ky = 0; ky < 5; ky++) {
            const float* r0 = pin + (cy0c + ky) * 13;
            const float* r1 = pin + (cy1 + ky) * 13;
#pragma unroll
            for (int kx = 0; kx < 5; kx++) {
                float i00 = r0[cx0c + kx];
                float i01 = r0[cx1 + kx];
                float i10 = r1[cx0c + kx];
                float i11 = r1[cx1 + kx];
#pragma unroll
                for (int j = 0; j < 4; j++) {
                    float wv = pw[j * 800 + ky * 5 + kx];
                    acc[j][0] += wv * i00; acc[j][1] += wv * i01;
                    acc[j][2] += wv * i10; acc[j][3] += wv * i11;
                }
            }
        }
    }
    float* o = g_a3 + (img0 + imgl) * 1024 + (ocg * 16 + ocq * 4) * 16 + py * 4 + px;
#pragma unroll
    for (int j = 0; j < 4; j++) {
        float m = acc[j][3];                       // (cy1, cx1) always valid
        if (vx) m = fmaxf(m, acc[j][2]);           // (cy1, cx0)
        if (vy) m = fmaxf(m, acc[j][1]);           // (cy0, cx1)
        if (vy && vx) m = fmaxf(m, acc[j][0]);     // (cy0, cx0)
        o[j * 16] = fmaxf(m, 0.f);
    }
}

// ---------------- fc1: [8192,1024] @ [256,1024]^T + bias, relu ----------------
__global__ void __launch_bounds__(256) k_fc1(const float* __restrict__ W,
                                             const float* __restrict__ bias) {
    __shared__ float As[16 * 68];
    __shared__ float Bs[16 * 68];
    const int tid = threadIdx.x;
    const int tx = tid & 15, ty = tid >> 4;
    const int m0 = blockIdx.y * 64;
    const int n0 = blockIdx.x * 64;
    const int lm = tid >> 2;            // 0..63
    const int lk = (tid & 3) * 4;       // 0,4,8,12
    const float* Ap = g_a3 + (m0 + lm) * 1024 + lk;
    const float* Wp = W + (n0 + lm) * 1024 + lk;

    float acc[4][4] = {};
    for (int k0 = 0; k0 < 1024; k0 += 16) {
        float4 av = *(const float4*)(Ap + k0);
        float4 bv = *(const float4*)(Wp + k0);
        As[(lk + 0) * 68 + lm] = av.x;
        As[(lk + 1) * 68 + lm] = av.y;
        As[(lk + 2) * 68 + lm] = av.z;
        As[(lk + 3) * 68 + lm] = av.w;
        Bs[(lk + 0) * 68 + lm] = bv.x;
        Bs[(lk + 1) * 68 + lm] = bv.y;
        Bs[(lk + 2) * 68 + lm] = bv.z;
        Bs[(lk + 3) * 68 + lm] = bv.w;
        __syncthreads();
#pragma unroll
        for (int k = 0; k < 16; k++) {
            float4 a = *(const float4*)&As[k * 68 + ty * 4];
            float4 b = *(const float4*)&Bs[k * 68 + tx * 4];
            acc[0][0] += a.x * b.x; acc[0][1] += a.x * b.y; acc[0][2] += a.x * b.z; acc[0][3] += a.x * b.w;
            acc[1][0] += a.y * b.x; acc[1][1] += a.y * b.y; acc[1][2] += a.y * b.z; acc[1][3] += a.y * b.w;
            acc[2][0] += a.z * b.x; acc[2][1] += a.z * b.y; acc[2][2] += a.z * b.z; acc[2][3] += a.z * b.w;
            acc[3][0] += a.w * b.x; acc[3][1] += a.w * b.y; acc[3][2] += a.w * b.z; acc[3][3] += a.w * b.w;
        }
        __syncthreads();
    }
#pragma unroll
    for (int i = 0; i < 4; i++) {
#pragma unroll
        for (int j = 0; j < 4; j++) {
            int n = n0 + tx * 4 + j;
            float v = acc[i][j] + bias[n];
            g_a4[(m0 + ty * 4 + i) * 256 + n] = fmaxf(v, 0.f);
        }
    }
}

// ---------------- fc2 ([8192,256] @ [10,256]^T + bias) + log_softmax ----------------
__global__ void __launch_bounds__(256) k_fc2(const float* __restrict__ W,
                                             const float* __restrict__ bias,
                                             float* __restrict__ out) {
    __shared__ float s_w[2560];
    __shared__ float s_b[10];
    const int tid = threadIdx.x;
    for (int i = tid; i < 2560; i += 256) s_w[i] = W[i];
    if (tid < 10) s_b[tid] = bias[tid];
    __syncthreads();

    const int warp = tid >> 5, lane = tid & 31;
    const int row = blockIdx.x * 8 + warp;
    float hv[8];
    const float* hp = g_a4 + row * 256 + lane;
#pragma unroll
    for (int j = 0; j < 8; j++) hv[j] = hp[j * 32];

    float acc[10];
#pragma unroll
    for (int o = 0; o < 10; o++) acc[o] = 0.f;
#pragma unroll
    for (int j = 0; j < 8; j++) {
#pragma unroll
        for (int o = 0; o < 10; o++)
            acc[o] += hv[j] * s_w[o * 256 + lane + j * 32];
    }
#pragma unroll
    for (int o = 0; o < 10; o++) {
#pragma unroll
        for (int off = 16; off > 0; off >>= 1)
            acc[o] += __shfl_xor_sync(0xffffffffu, acc[o], off);
    }
    if (lane == 0) {
        float l[10], m = -1e30f;
#pragma unroll
        for (int o = 0; o < 10; o++) { l[o] = acc[o] + s_b[o]; m = fmaxf(m, l[o]); }
        float s = 0.f;
#pragma unroll
        for (int o = 0; o < 10; o++) s += expf(l[o] - m);
        float ls = logf(s);
        float* op = out + row * 10;
#pragma unroll
        for (int o = 0; o < 10; o++) op[o] = l[o] - m - ls;
    }
}

extern "C" void kernel_launch(void* const* d_in, const int* in_sizes, int n_in,
                              void* d_out, int out_size) {
    const float* x   = (const float*)d_in[0];
    const float* w1  = (const float*)d_in[1];
    const float* b1  = (const float*)d_in[2];
    const float* w2  = (const float*)d_in[3];
    const float* b2  = (const float*)d_in[4];
    const float* w3  = (const float*)d_in[5];
    const float* b3  = (const float*)d_in[6];
    const float* fw1 = (const float*)d_in[7];
    const float* fb1 = (const float*)d_in[8];
    const float* fw2 = (const float*)d_in[9];
    const float* fb2 = (const float*)d_in[10];
    float* out = (float*)d_out;

    const int smem2 = 18304 * 4;   // 73216 B
    const int smem3 = 31120 * 4;   // 124480 B
    cudaFuncSetAttribute(k_conv2, cudaFuncAttributeMaxDynamicSharedMemorySize, smem2);
    cudaFuncSetAttribute(k_conv3, cudaFuncAttributeMaxDynamicSharedMemorySize, smem3);

    k_conv1<<<BATCH, 224>>>(x, w1, b1);
    k_conv2<<<BATCH, 224, smem2>>>(w2, b2);
    k_conv3<<<dim3(BATCH / 4, 4), 256, smem3>>>(w3, b3);
    k_fc1<<<dim3(256 / 64, BATCH / 64), 256>>>(fw1, fb1);
    k_fc2<<<BATCH / 8, 256>>>(fw2, fb2, out);
}

// round 2
// speedup vs baseline: 2.6930x; 2.6930x over previous
#include <cuda_runtime.h>
#include <cuda_bf16.h>
#include <math.h>
#include <stdint.h>

#define BATCH 8192

// Scratch (device globals; no allocation allowed)
__device__ float g_a1[BATCH * 16 * 14 * 14];  // conv1+pool out, [b][ic*196+px]
__device__ float g_a2[BATCH * 32 * 7 * 7];    // conv2+pool out, [b][px*32+ic] (px=0..48)
__device__ float g_a3[BATCH * 1024];          // conv3+pool out, [b][1024]
__device__ float g_a4[BATCH * 256];           // fc1 out

// ---------------- helpers ----------------
__device__ __forceinline__ void bf16split(float v, __nv_bfloat16& h, __nv_bfloat16& l) {
    h = __float2bfloat16(v);
    l = __float2bfloat16(v - __bfloat162float(h));
}

__device__ __forceinline__ void mma_bf16(float* c,
                                         uint32_t a0, uint32_t a1, uint32_t a2, uint32_t a3,
                                         uint32_t b0, uint32_t b1) {
    asm volatile(
        "mma.sync.aligned.m16n8k16.row.col.f32.bf16.bf16.f32 "
        "{%0,%1,%2,%3}, {%4,%5,%6,%7}, {%8,%9}, {%0,%1,%2,%3};"
        : "+f"(c[0]), "+f"(c[1]), "+f"(c[2]), "+f"(c[3])
        : "r"(a0), "r"(a1), "r"(a2), "r"(a3), "r"(b0), "r"(b1));
}

__device__ __forceinline__ uint32_t lds_u32(const __nv_bfloat16* p, int elem_idx) {
    return *reinterpret_cast<const uint32_t*>(p + elem_idx);
}

// ---------------- conv1 (1->16, 5x5, pad2) + relu + maxpool2 (FFMA) ----------------
__global__ void __launch_bounds__(224) k_conv1(const float* __restrict__ x,
                                               const float* __restrict__ w1,
                                               const float* __restrict__ b1) {
    __shared__ float s_in[32 * 33];
    __shared__ float s_w[400];
    __shared__ float s_b[16];
    const int img = blockIdx.x;
    const int tid = threadIdx.x;

    for (int i = tid; i < 32 * 33; i += 224) s_in[i] = 0.f;
    for (int i = tid; i < 400; i += 224) s_w[i] = w1[i];
    if (tid < 16) s_b[tid] = b1[tid];
    __syncthreads();
    const float* xin = x + img * 784;
    for (int i = tid; i < 784; i += 224) {
        int r = i / 28, c = i - r * 28;
        s_in[(r + 2) * 33 + (c + 2)] = xin[i];
    }
    __syncthreads();

    if (tid < 196) {
        int py = tid / 14, px = tid - py * 14;
        int y0 = 2 * py, x0 = 2 * px;
        float acc[16][4];
#pragma unroll
        for (int j = 0; j < 16; j++) {
            float bv = s_b[j];
            acc[j][0] = bv; acc[j][1] = bv; acc[j][2] = bv; acc[j][3] = bv;
        }
#pragma unroll
        for (int ky = 0; ky < 5; ky++) {
            const float* r0 = &s_in[(y0 + ky) * 33 + x0];
            const float* r1 = r0 + 33;
#pragma unroll
            for (int kx = 0; kx < 5; kx++) {
                float i0 = r0[kx], i1 = r0[kx + 1], i2 = r1[kx], i3 = r1[kx + 1];
#pragma unroll
                for (int j = 0; j < 16; j++) {
                    float wv = s_w[j * 25 + ky * 5 + kx];
                    acc[j][0] += wv * i0; acc[j][1] += wv * i1;
                    acc[j][2] += wv * i2; acc[j][3] += wv * i3;
                }
            }
        }
        float* o = g_a1 + img * 3136 + py * 14 + px;
#pragma unroll
        for (int j = 0; j < 16; j++) {
            float m = fmaxf(fmaxf(acc[j][0], acc[j][1]), fmaxf(acc[j][2], acc[j][3]));
            o[j * 196] = fmaxf(m, 0.f);
        }
    }
}

// ---------------- conv2 (16->32) via bf16x3 tensor MMA + fused relu+pool ----------------
// Block: 2 images, 256 threads (8 warps), N=32 oc, K=400 (25 k16 steps).
// SMEM bytes: inh 24624 | inl 24624 | wh 25728 | wl 25728 | pool 12544 | bias 128 = 113376
#define C2_SMEM 113376
__global__ void __launch_bounds__(256, 2) k_conv2(const float* __restrict__ w2,
                                                  const float* __restrict__ b2) {
    extern __shared__ char smem[];
    __nv_bfloat16* s_inh = (__nv_bfloat16*)(smem);             // 2*6156 elems
    __nv_bfloat16* s_inl = (__nv_bfloat16*)(smem + 24624);
    __nv_bfloat16* s_wh  = (__nv_bfloat16*)(smem + 49248);     // 32*402
    __nv_bfloat16* s_wl  = (__nv_bfloat16*)(smem + 74976);
    int*           s_pool = (int*)(smem + 100704);             // 2*49*32
    float*         s_bias = (float*)(smem + 113248);

    const int img0 = blockIdx.x * 2;
    const int tid = threadIdx.x;
    const int warp = tid >> 5;
    const int lane = tid & 31;
    const int gid = lane >> 2;       // 0..7
    const int tg  = lane & 3;        // 0..3
    const int kk  = tg * 2;

    // zero input planes + pool
    uint32_t* zin = (uint32_t*)smem;
    for (int i = tid; i < 12312; i += 256) zin[i] = 0u;
    for (int i = tid; i < 3136; i += 256) s_pool[i] = 0;
    if (tid < 32) s_bias[tid] = b2[tid];
    // weights: w2[oc][ic][25] -> s_w[oc*402 + off*16 + ic], split hi/lo
    for (int i = tid; i < 12800; i += 256) {
        int oc = i / 400, r = i - oc * 400;
        int ic = r / 25, off = r - ic * 25;
        __nv_bfloat16 h, l;
        bf16split(w2[i], h, l);
        int d = oc * 402 + off * 16 + ic;
        s_wh[d] = h; s_wl[d] = l;
    }
    __syncthreads();
    // input: g_a1[img][ic*196+px] -> s_in[img*6156 + ((r+2)*19 + (c+2))*18 + ic]
    for (int i = tid; i < 6272; i += 256) {
        int img = i / 3136, idx = i - img * 3136;
        int ic = idx / 196, p = idx - ic * 196;
        int r = p / 14, c = p - r * 14;
        __nv_bfloat16 h, l;
        bf16split(g_a1[(img0 + img) * 3136 + idx], h, l);
        int d = img * 6156 + ((r + 2) * 19 + (c + 2)) * 18 + ic;
        s_inh[d] = h; s_inl[d] = l;
    }
    __syncthreads();

    // m-tiles: 26 (2 img x 13 tiles of 16 px over 196), warp w owns t = w, w+8, w+16, w+24
    int aoff0[4], aoff1[4];
#pragma unroll
    for (int ti = 0; ti < 4; ti++) {
        int t = warp + 8 * ti;
        if (t < 26) {
            int img = t / 13, base = (t - img * 13) * 16;
            int p0 = base + gid; if (p0 > 195) p0 = 195;
            int p1 = base + gid + 8; if (p1 > 195) p1 = 195;
            int y0 = p0 / 14, x0 = p0 - y0 * 14;
            int y1 = p1 / 14, x1 = p1 - y1 * 14;
            aoff0[ti] = img * 6156 + (y0 * 19 + x0) * 18;
            aoff1[ti] = img * 6156 + (y1 * 19 + x1) * 18;
        }
    }

    float acc[4][4][4];
#pragma unroll
    for (int ti = 0; ti < 4; ti++)
#pragma unroll
        for (int nt = 0; nt < 4; nt++)
#pragma unroll
            for (int j = 0; j < 4; j++) acc[ti][nt][j] = 0.f;

#pragma unroll 1
    for (int off = 0; off < 25; off++) {
        int dy = off / 5, dx = off - dy * 5;
        int dbase = (dy * 19 + dx) * 18 + kk;
        uint32_t bh0[4], bh1[4], bl0[4], bl1[4];
#pragma unroll
        for (int nt = 0; nt < 4; nt++) {
            int wr = (nt * 8 + gid) * 402 + off * 16 + kk;
            bh0[nt] = lds_u32(s_wh, wr); bh1[nt] = lds_u32(s_wh, wr + 8);
            bl0[nt] = lds_u32(s_wl, wr); bl1[nt] = lds_u32(s_wl, wr + 8);
        }
#pragma unroll
        for (int ti = 0; ti < 4; ti++) {
            int t = warp + 8 * ti;
            if (t < 26) {
                int o0 = aoff0[ti] + dbase;
                int o1 = aoff1[ti] + dbase;
                uint32_t ah0 = lds_u32(s_inh, o0), ah1 = lds_u32(s_inh, o1);
                uint32_t ah2 = lds_u32(s_inh, o0 + 8), ah3 = lds_u32(s_inh, o1 + 8);
                uint32_t al0 = lds_u32(s_inl, o0), al1 = lds_u32(s_inl, o1);
                uint32_t al2 = lds_u32(s_inl, o0 + 8), al3 = lds_u32(s_inl, o1 + 8);
#pragma unroll
                for (int nt = 0; nt < 4; nt++) {
                    mma_bf16(acc[ti][nt], ah0, ah1, ah2, ah3, bh0[nt], bh1[nt]);
                    mma_bf16(acc[ti][nt], ah0, ah1, ah2, ah3, bl0[nt], bl1[nt]);
                    mma_bf16(acc[ti][nt], al0, al1, al2, al3, bh0[nt], bh1[nt]);
                }
            }
        }
    }

    // epilogue: bias + relu, fused maxpool via shared atomicMax on float bits (vals >= 0)
#pragma unroll
    for (int ti = 0; ti < 4; ti++) {
        int t = warp + 8 * ti;
        if (t < 26) {
            int img = t / 13, base = (t - img * 13) * 16;
            int p0 = base + gid, p1 = p0 + 8;
#pragma unroll
            for (int nt = 0; nt < 4; nt++) {
                int col = nt * 8 + kk;
                float bb0 = s_bias[col], bb1 = s_bias[col + 1];
                if (p0 < 196) {
                    int y = p0 / 14, x = p0 - y * 14;
                    int pi = img * 1568 + ((y >> 1) * 7 + (x >> 1)) * 32;
                    float v0 = fmaxf(acc[ti][nt][0] + bb0, 0.f);
                    float v1 = fmaxf(acc[ti][nt][1] + bb1, 0.f);
                    atomicMax(&s_pool[pi + col], __float_as_int(v0));
                    atomicMax(&s_pool[pi + col + 1], __float_as_int(v1));
                }
                if (p1 < 196) {
                    int y = p1 / 14, x = p1 - y * 14;
                    int pi = img * 1568 + ((y >> 1) * 7 + (x >> 1)) * 32;
                    float v2 = fmaxf(acc[ti][nt][2] + bb0, 0.f);
                    float v3 = fmaxf(acc[ti][nt][3] + bb1, 0.f);
                    atomicMax(&s_pool[pi + col], __float_as_int(v2));
                    atomicMax(&s_pool[pi + col + 1], __float_as_int(v3));
                }
            }
        }
    }
    __syncthreads();
    for (int j = tid; j < 3136; j += 256) {
        int img = j / 1568, rem = j - img * 1568;
        g_a2[(img0 + img) * 1568 + rem] = __int_as_float(s_pool[j]);
    }
}

// ---------------- conv3 (32->64) via bf16x3 tensor MMA + fused relu+pool(pad1) ----------------
// Block: 4 images x 32-oc group, 256 threads, K=800 (50 k16 steps).
// SMEM bytes: inh 35904 | inl 35904 | wh 51328 | wl 51328 | pool 8192 | bias 128 = 182784
#define C3_SMEM 182784
__global__ void __launch_bounds__(256, 1) k_conv3(const float* __restrict__ w3,
                                                  const float* __restrict__ b3) {
    extern __shared__ char smem[];
    __nv_bfloat16* s_inh = (__nv_bfloat16*)(smem);             // 4*4488 elems
    __nv_bfloat16* s_inl = (__nv_bfloat16*)(smem + 35904);
    __nv_bfloat16* s_wh  = (__nv_bfloat16*)(smem + 71808);     // 32*802
    __nv_bfloat16* s_wl  = (__nv_bfloat16*)(smem + 123136);
    int*           s_pool = (int*)(smem + 174464);             // 4*16*32
    float*         s_bias = (float*)(smem + 182656);

    const int img0 = blockIdx.x * 4;
    const int g = blockIdx.y;        // oc-group: 0 or 1
    const int tid = threadIdx.x;
    const int warp = tid >> 5;
    const int lane = tid & 31;
    const int gid = lane >> 2;
    const int tg  = lane & 3;
    const int kk  = tg * 2;

    uint32_t* zin = (uint32_t*)smem;
    for (int i = tid; i < 17952; i += 256) zin[i] = 0u;
    for (int i = tid; i < 2048; i += 256) s_pool[i] = 0;
    if (tid < 32) s_bias[tid] = b3[g * 32 + tid];
    // weights: w3[(g*32+ocl)][ic][25] -> s_w[ocl*802 + off*32 + ic]
    const float* wg = w3 + g * 32 * 800;
    for (int i = tid; i < 25600; i += 256) {
        int ocl = i / 800, r = i - ocl * 800;
        int ic = r / 25, off = r - ic * 25;
        __nv_bfloat16 h, l;
        bf16split(wg[i], h, l);
        int d = ocl * 802 + off * 32 + ic;
        s_wh[d] = h; s_wl[d] = l;
    }
    __syncthreads();
    // input: g_a2[img][px*32+ic] (px=0..48) -> s_in[img*4488 + ((y+2)*12 + (x+2))*34 + ic]
    for (int i = tid; i < 6272; i += 256) {
        int img = i / 1568, rem = i - img * 1568;
        int p = rem / 32, ic = rem - p * 32;
        int y = p / 7, x = p - y * 7;
        __nv_bfloat16 h, l;
        bf16split(g_a2[(img0 + img) * 1568 + rem], h, l);
        int d = img * 4488 + ((y + 2) * 12 + (x + 2)) * 34 + ic;
        s_inh[d] = h; s_inl[d] = l;
    }
    __syncthreads();

    // m-tiles: 16 (4 img x 4 tiles of 16 px covering 49), warp w owns t = w, w+8
    int aoff0[2], aoff1[2];
#pragma unroll
    for (int ti = 0; ti < 2; ti++) {
        int t = warp + 8 * ti;
        int img = t >> 2, base = (t & 3) * 16;
        int p0 = base + gid; if (p0 > 48) p0 = 48;
        int p1 = base + gid + 8; if (p1 > 48) p1 = 48;
        int y0 = p0 / 7, x0 = p0 - y0 * 7;
        int y1 = p1 / 7, x1 = p1 - y1 * 7;
        aoff0[ti] = img * 4488 + (y0 * 12 + x0) * 34;
        aoff1[ti] = img * 4488 + (y1 * 12 + x1) * 34;
    }

    float acc[2][4][4];
#pragma unroll
    for (int ti = 0; ti < 2; ti++)
#pragma unroll
        for (int nt = 0; nt < 4; nt++)
#pragma unroll
            for (int j = 0; j < 4; j++) acc[ti][nt][j] = 0.f;

#pragma unroll 1
    for (int s = 0; s < 50; s++) {
        int off = s >> 1;
        int ich = (s & 1) * 16;
        int dy = off / 5, dx = off - dy * 5;
        int dbase = (dy * 12 + dx) * 34 + ich + kk;
        uint32_t bh0[4], bh1[4], bl0[4], bl1[4];
#pragma unroll
        for (int nt = 0; nt < 4; nt++) {
            int wr = (nt * 8 + gid) * 802 + off * 32 + ich + kk;
            bh0[nt] = lds_u32(s_wh, wr); bh1[nt] = lds_u32(s_wh, wr + 8);
            bl0[nt] = lds_u32(s_wl, wr); bl1[nt] = lds_u32(s_wl, wr + 8);
        }
#pragma unroll
        for (int ti = 0; ti < 2; ti++) {
            int o0 = aoff0[ti] + dbase;
            int o1 = aoff1[ti] + dbase;
            uint32_t ah0 = lds_u32(s_inh, o0), ah1 = lds_u32(s_inh, o1);
            uint32_t ah2 = lds_u32(s_inh, o0 + 8), ah3 = lds_u32(s_inh, o1 + 8);
            uint32_t al0 = lds_u32(s_inl, o0), al1 = lds_u32(s_inl, o1);
            uint32_t al2 = lds_u32(s_inl, o0 + 8), al3 = lds_u32(s_inl, o1 + 8);
#pragma unroll
            for (int nt = 0; nt < 4; nt++) {
                mma_bf16(acc[ti][nt], ah0, ah1, ah2, ah3, bh0[nt], bh1[nt]);
                mma_bf16(acc[ti][nt], ah0, ah1, ah2, ah3, bl0[nt], bl1[nt]);
                mma_bf16(acc[ti][nt], al0, al1, al2, al3, bh0[nt], bh1[nt]);
            }
        }
    }

    // epilogue: bias + relu, fused pool (pad=1): pooled (py,px) = ((y+1)/2, (x+1)/2)
#pragma unroll
    for (int ti = 0; ti < 2; ti++) {
        int t = warp + 8 * ti;
        int img = t >> 2, base = (t & 3) * 16;
        int p0 = base + gid, p1 = p0 + 8;
#pragma unroll
        for (int nt = 0; nt < 4; nt++) {
            int col = nt * 8 + kk;
            float bb0 = s_bias[col], bb1 = s_bias[col + 1];
            if (p0 < 49) {
                int y = p0 / 7, x = p0 - y * 7;
                int pi = img * 512 + (((y + 1) >> 1) * 4 + ((x + 1) >> 1)) * 32;
                float v0 = fmaxf(acc[ti][nt][0] + bb0, 0.f);
                float v1 = fmaxf(acc[ti][nt][1] + bb1, 0.f);
                atomicMax(&s_pool[pi + col], __float_as_int(v0));
                atomicMax(&s_pool[pi + col + 1], __float_as_int(v1));
            }
            if (p1 < 49) {
                int y = p1 / 7, x = p1 - y * 7;
                int pi = img * 512 + (((y + 1) >> 1) * 4 + ((x + 1) >> 1)) * 32;
                float v2 = fmaxf(acc[ti][nt][2] + bb0, 0.f);
                float v3 = fmaxf(acc[ti][nt][3] + bb1, 0.f);
                atomicMax(&s_pool[pi + col], __float_as_int(v2));
                atomicMax(&s_pool[pi + col + 1], __float_as_int(v3));
            }
        }
    }
    __syncthreads();
    // s_pool[img][pidx*32 + ocl] -> g_a3[b][ (g*32+ocl)*16 + pidx ]
    for (int j = tid; j < 2048; j += 256) {
        int img = j >> 9, rem = j & 511;
        int pidx = rem >> 5, ocl = rem & 31;
        g_a3[(img0 + img) * 1024 + (g * 32 + ocl) * 16 + pidx] = __int_as_float(s_pool[j]);
    }
}

// ---------------- fc1: [8192,1024] @ [256,1024]^T + bias, relu (FFMA) ----------------
__global__ void __launch_bounds__(256) k_fc1(const float* __restrict__ W,
                                             const float* __restrict__ bias) {
    __shared__ float As[16 * 68];
    __shared__ float Bs[16 * 68];
    const int tid = threadIdx.x;
    const int tx = tid & 15, ty = tid >> 4;
    const int m0 = blockIdx.y * 64;
    const int n0 = blockIdx.x * 64;
    const int lm = tid >> 2;
    const int lk = (tid & 3) * 4;
    const float* Ap = g_a3 + (m0 + lm) * 1024 + lk;
    const float* Wp = W + (n0 + lm) * 1024 + lk;

    float acc[4][4] = {};
    for (int k0 = 0; k0 < 1024; k0 += 16) {
        float4 av = *(const float4*)(Ap + k0);
        float4 bv = *(const float4*)(Wp + k0);
        As[(lk + 0) * 68 + lm] = av.x;
        As[(lk + 1) * 68 + lm] = av.y;
        As[(lk + 2) * 68 + lm] = av.z;
        As[(lk + 3) * 68 + lm] = av.w;
        Bs[(lk + 0) * 68 + lm] = bv.x;
        Bs[(lk + 1) * 68 + lm] = bv.y;
        Bs[(lk + 2) * 68 + lm] = bv.z;
        Bs[(lk + 3) * 68 + lm] = bv.w;
        __syncthreads();
#pragma unroll
        for (int k = 0; k < 16; k++) {
            float4 a = *(const float4*)&As[k * 68 + ty * 4];
            float4 b = *(const float4*)&Bs[k * 68 + tx * 4];
            acc[0][0] += a.x * b.x; acc[0][1] += a.x * b.y; acc[0][2] += a.x * b.z; acc[0][3] += a.x * b.w;
            acc[1][0] += a.y * b.x; acc[1][1] += a.y * b.y; acc[1][2] += a.y * b.z; acc[1][3] += a.y * b.w;
            acc[2][0] += a.z * b.x; acc[2][1] += a.z * b.y; acc[2][2] += a.z * b.z; acc[2][3] += a.z * b.w;
            acc[3][0] += a.w * b.x; acc[3][1] += a.w * b.y; acc[3][2] += a.w * b.z; acc[3][3] += a.w * b.w;
        }
        __syncthreads();
    }
#pragma unroll
    for (int i = 0; i < 4; i++) {
#pragma unroll
        for (int j = 0; j < 4; j++) {
            int n = n0 + tx * 4 + j;
            float v = acc[i][j] + bias[n];
            g_a4[(m0 + ty * 4 + i) * 256 + n] = fmaxf(v, 0.f);
        }
    }
}

// ---------------- fc2 + log_softmax ----------------
__global__ void __launch_bounds__(256) k_fc2(const float* __restrict__ W,
                                             const float* __restrict__ bias,
                                             float* __restrict__ out) {
    __shared__ float s_w[2560];
    __shared__ float s_b[10];
    const int tid = threadIdx.x;
    for (int i = tid; i < 2560; i += 256) s_w[i] = W[i];
    if (tid < 10) s_b[tid] = bias[tid];
    __syncthreads();

    const int warp = tid >> 5, lane = tid & 31;
    const int row = blockIdx.x * 8 + warp;
    float hv[8];
    const float* hp = g_a4 + row * 256 + lane;
#pragma unroll
    for (int j = 0; j < 8; j++) hv[j] = hp[j * 32];

    float acc[10];
#pragma unroll
    for (int o = 0; o < 10; o++) acc[o] = 0.f;
#pragma unroll
    for (int j = 0; j < 8; j++) {
#pragma unroll
        for (int o = 0; o < 10; o++)
            acc[o] += hv[j] * s_w[o * 256 + lane + j * 32];
    }
#pragma unroll
    for (int o = 0; o < 10; o++) {
#pragma unroll
        for (int off = 16; off > 0; off >>= 1)
            acc[o] += __shfl_xor_sync(0xffffffffu, acc[o], off);
    }
    if (lane == 0) {
        float l[10], m = -1e30f;
#pragma unroll
        for (int o = 0; o < 10; o++) { l[o] = acc[o] + s_b[o]; m = fmaxf(m, l[o]); }
        float s = 0.f;
#pragma unroll
        for (int o = 0; o < 10; o++) s += expf(l[o] - m);
        float ls = logf(s);
        float* op = out + row * 10;
#pragma unroll
        for (int o = 0; o < 10; o++) op[o] = l[o] - m - ls;
    }
}

extern "C" void kernel_launch(void* const* d_in, const int* in_sizes, int n_in,
                              void* d_out, int out_size) {
    const float* x   = (const float*)d_in[0];
    const float* w1  = (const float*)d_in[1];
    const float* b1  = (const float*)d_in[2];
    const float* w2  = (const float*)d_in[3];
    const float* b2  = (const float*)d_in[4];
    const float* w3  = (const float*)d_in[5];
    const float* b3  = (const float*)d_in[6];
    const float* fw1 = (const float*)d_in[7];
    const float* fb1 = (const float*)d_in[8];
    const float* fw2 = (const float*)d_in[9];
    const float* fb2 = (const float*)d_in[10];
    float* out = (float*)d_out;

    cudaFuncSetAttribute(k_conv2, cudaFuncAttributeMaxDynamicSharedMemorySize, C2_SMEM);
    cudaFuncSetAttribute(k_conv3, cudaFuncAttributeMaxDynamicSharedMemorySize, C3_SMEM);

    k_conv1<<<BATCH, 224>>>(x, w1, b1);
    k_conv2<<<BATCH / 2, 256, C2_SMEM>>>(w2, b2);
    k_conv3<<<dim3(BATCH / 4, 2), 256, C3_SMEM>>>(w3, b3);
    k_fc1<<<dim3(256 / 64, BATCH / 64), 256>>>(fw1, fb1);
    k_fc2<<<BATCH / 8, 256>>>(fw2, fb2, out);
}

// round 3
// speedup vs baseline: 2.7677x; 1.0277x over previous
#include <cuda_runtime.h>
#include <cuda_bf16.h>
#include <math.h>
#include <stdint.h>

#define BATCH 8192

// Scratch (device globals; no allocation allowed) — activations stored as bf16 hi/lo pairs
__device__ __nv_bfloat16 g_a1h[BATCH * 3136];  // conv1+pool out hi
__device__ __nv_bfloat16 g_a1l[BATCH * 3136];  // conv1+pool out lo
__device__ __nv_bfloat16 g_a2h[BATCH * 1568];  // conv2+pool out, [b][px*32+ic]
__device__ __nv_bfloat16 g_a2l[BATCH * 1568];
__device__ __nv_bfloat16 g_a3h[BATCH * 1024];  // conv3+pool out (flattened)
__device__ __nv_bfloat16 g_a3l[BATCH * 1024];
__device__ float g_a4[BATCH * 256];            // fc1 out
__device__ __nv_bfloat16 g_fw1h[256 * 1024];   // fc1 weights split
__device__ __nv_bfloat16 g_fw1l[256 * 1024];

// ---------------- helpers ----------------
__device__ __forceinline__ void bf16split(float v, __nv_bfloat16& h, __nv_bfloat16& l) {
    h = __float2bfloat16(v);
    l = __float2bfloat16(v - __bfloat162float(h));
}

__device__ __forceinline__ void mma_bf16(float* c,
                                         uint32_t a0, uint32_t a1, uint32_t a2, uint32_t a3,
                                         uint32_t b0, uint32_t b1) {
    asm volatile(
        "mma.sync.aligned.m16n8k16.row.col.f32.bf16.bf16.f32 "
        "{%0,%1,%2,%3}, {%4,%5,%6,%7}, {%8,%9}, {%0,%1,%2,%3};"
        : "+f"(c[0]), "+f"(c[1]), "+f"(c[2]), "+f"(c[3])
        : "r"(a0), "r"(a1), "r"(a2), "r"(a3), "r"(b0), "r"(b1));
}

__device__ __forceinline__ uint32_t lds_u32(const __nv_bfloat16* p, int elem_idx) {
    return *reinterpret_cast<const uint32_t*>(p + elem_idx);
}

// ---------------- k_prep: split fc1 weights into bf16 hi/lo ----------------
__global__ void __launch_bounds__(256) k_prep(const float* __restrict__ fw1) {
    int i = blockIdx.x * 256 + threadIdx.x;   // grid covers 262144
    float v = fw1[i];
    __nv_bfloat16 h, l;
    bf16split(v, h, l);
    g_fw1h[i] = h; g_fw1l[i] = l;
}

// ---------------- conv1 (1->16, 5x5, pad2) + relu + maxpool2 (FFMA) ----------------
__global__ void __launch_bounds__(224) k_conv1(const float* __restrict__ x,
                                               const float* __restrict__ w1,
                                               const float* __restrict__ b1) {
    __shared__ float s_in[32 * 33];
    __shared__ float s_w[400];
    __shared__ float s_b[16];
    const int img = blockIdx.x;
    const int tid = threadIdx.x;

    for (int i = tid; i < 32 * 33; i += 224) s_in[i] = 0.f;
    for (int i = tid; i < 400; i += 224) s_w[i] = w1[i];
    if (tid < 16) s_b[tid] = b1[tid];
    __syncthreads();
    const float* xin = x + img * 784;
    for (int i = tid; i < 784; i += 224) {
        int r = i / 28, c = i - r * 28;
        s_in[(r + 2) * 33 + (c + 2)] = xin[i];
    }
    __syncthreads();

    if (tid < 196) {
        int py = tid / 14, px = tid - py * 14;
        int y0 = 2 * py, x0 = 2 * px;
        float acc[16][4];
#pragma unroll
        for (int j = 0; j < 16; j++) {
            float bv = s_b[j];
            acc[j][0] = bv; acc[j][1] = bv; acc[j][2] = bv; acc[j][3] = bv;
        }
#pragma unroll
        for (int ky = 0; ky < 5; ky++) {
            const float* r0 = &s_in[(y0 + ky) * 33 + x0];
            const float* r1 = r0 + 33;
#pragma unroll
            for (int kx = 0; kx < 5; kx++) {
                float i0 = r0[kx], i1 = r0[kx + 1], i2 = r1[kx], i3 = r1[kx + 1];
#pragma unroll
                for (int j = 0; j < 16; j++) {
                    float wv = s_w[j * 25 + ky * 5 + kx];
                    acc[j][0] += wv * i0; acc[j][1] += wv * i1;
                    acc[j][2] += wv * i2; acc[j][3] += wv * i3;
                }
            }
        }
        int dbase = img * 3136 + py * 14 + px;
#pragma unroll
        for (int j = 0; j < 16; j++) {
            float m = fmaxf(fmaxf(acc[j][0], acc[j][1]), fmaxf(acc[j][2], acc[j][3]));
            m = fmaxf(m, 0.f);
            __nv_bfloat16 h, l;
            bf16split(m, h, l);
            g_a1h[dbase + j * 196] = h;
            g_a1l[dbase + j * 196] = l;
        }
    }
}

// ---------------- conv2 (16->32) via bf16x3 tensor MMA + fused relu+pool ----------------
#define C2_SMEM 113376
__global__ void __launch_bounds__(256, 2) k_conv2(const float* __restrict__ w2,
                                                  const float* __restrict__ b2) {
    extern __shared__ char smem[];
    __nv_bfloat16* s_inh = (__nv_bfloat16*)(smem);             // 2*6156 elems
    __nv_bfloat16* s_inl = (__nv_bfloat16*)(smem + 24624);
    __nv_bfloat16* s_wh  = (__nv_bfloat16*)(smem + 49248);     // 32*402
    __nv_bfloat16* s_wl  = (__nv_bfloat16*)(smem + 74976);
    int*           s_pool = (int*)(smem + 100704);             // 2*49*32
    float*         s_bias = (float*)(smem + 113248);

    const int img0 = blockIdx.x * 2;
    const int tid = threadIdx.x;
    const int warp = tid >> 5;
    const int lane = tid & 31;
    const int gid = lane >> 2;
    const int tg  = lane & 3;
    const int kk  = tg * 2;

    uint32_t* zin = (uint32_t*)smem;
    for (int i = tid; i < 12312; i += 256) zin[i] = 0u;
    for (int i = tid; i < 3136; i += 256) s_pool[i] = 0;
    if (tid < 32) s_bias[tid] = b2[tid];
    for (int i = tid; i < 12800; i += 256) {
        int oc = i / 400, r = i - oc * 400;
        int ic = r / 25, off = r - ic * 25;
        __nv_bfloat16 h, l;
        bf16split(w2[i], h, l);
        int d = oc * 402 + off * 16 + ic;
        s_wh[d] = h; s_wl[d] = l;
    }
    __syncthreads();
    for (int i = tid; i < 6272; i += 256) {
        int img = i / 3136, idx = i - img * 3136;
        int ic = idx / 196, p = idx - ic * 196;
        int r = p / 14, c = p - r * 14;
        int src = (img0 + img) * 3136 + idx;
        int d = img * 6156 + ((r + 2) * 19 + (c + 2)) * 18 + ic;
        s_inh[d] = g_a1h[src];
        s_inl[d] = g_a1l[src];
    }
    __syncthreads();

    int aoff0[4], aoff1[4];
#pragma unroll
    for (int ti = 0; ti < 4; ti++) {
        int t = warp + 8 * ti;
        if (t < 26) {
            int img = t / 13, base = (t - img * 13) * 16;
            int p0 = base + gid; if (p0 > 195) p0 = 195;
            int p1 = base + gid + 8; if (p1 > 195) p1 = 195;
            int y0 = p0 / 14, x0 = p0 - y0 * 14;
            int y1 = p1 / 14, x1 = p1 - y1 * 14;
            aoff0[ti] = img * 6156 + (y0 * 19 + x0) * 18;
            aoff1[ti] = img * 6156 + (y1 * 19 + x1) * 18;
        }
    }

    float acc[4][4][4];
#pragma unroll
    for (int ti = 0; ti < 4; ti++)
#pragma unroll
        for (int nt = 0; nt < 4; nt++)
#pragma unroll
            for (int j = 0; j < 4; j++) acc[ti][nt][j] = 0.f;

#pragma unroll 1
    for (int off = 0; off < 25; off++) {
        int dy = off / 5, dx = off - dy * 5;
        int dbase = (dy * 19 + dx) * 18 + kk;
        uint32_t bh0[4], bh1[4], bl0[4], bl1[4];
#pragma unroll
        for (int nt = 0; nt < 4; nt++) {
            int wr = (nt * 8 + gid) * 402 + off * 16 + kk;
            bh0[nt] = lds_u32(s_wh, wr); bh1[nt] = lds_u32(s_wh, wr + 8);
            bl0[nt] = lds_u32(s_wl, wr); bl1[nt] = lds_u32(s_wl, wr + 8);
        }
#pragma unroll
        for (int ti = 0; ti < 4; ti++) {
            int t = warp + 8 * ti;
            if (t < 26) {
                int o0 = aoff0[ti] + dbase;
                int o1 = aoff1[ti] + dbase;
                uint32_t ah0 = lds_u32(s_inh, o0), ah1 = lds_u32(s_inh, o1);
                uint32_t ah2 = lds_u32(s_inh, o0 + 8), ah3 = lds_u32(s_inh, o1 + 8);
                uint32_t al0 = lds_u32(s_inl, o0), al1 = lds_u32(s_inl, o1);
                uint32_t al2 = lds_u32(s_inl, o0 + 8), al3 = lds_u32(s_inl, o1 + 8);
                // independent consecutive mmas: term-major order
#pragma unroll
                for (int nt = 0; nt < 4; nt++)
                    mma_bf16(acc[ti][nt], ah0, ah1, ah2, ah3, bh0[nt], bh1[nt]);
#pragma unroll
                for (int nt = 0; nt < 4; nt++)
                    mma_bf16(acc[ti][nt], ah0, ah1, ah2, ah3, bl0[nt], bl1[nt]);
#pragma unroll
                for (int nt = 0; nt < 4; nt++)
                    mma_bf16(acc[ti][nt], al0, al1, al2, al3, bh0[nt], bh1[nt]);
            }
        }
    }

#pragma unroll
    for (int ti = 0; ti < 4; ti++) {
        int t = warp + 8 * ti;
        if (t < 26) {
            int img = t / 13, base = (t - img * 13) * 16;
            int p0 = base + gid, p1 = p0 + 8;
#pragma unroll
            for (int nt = 0; nt < 4; nt++) {
                int col = nt * 8 + kk;
                float bb0 = s_bias[col], bb1 = s_bias[col + 1];
                if (p0 < 196) {
                    int y = p0 / 14, x = p0 - y * 14;
                    int pi = img * 1568 + ((y >> 1) * 7 + (x >> 1)) * 32;
                    atomicMax(&s_pool[pi + col], __float_as_int(fmaxf(acc[ti][nt][0] + bb0, 0.f)));
                    atomicMax(&s_pool[pi + col + 1], __float_as_int(fmaxf(acc[ti][nt][1] + bb1, 0.f)));
                }
                if (p1 < 196) {
                    int y = p1 / 14, x = p1 - y * 14;
                    int pi = img * 1568 + ((y >> 1) * 7 + (x >> 1)) * 32;
                    atomicMax(&s_pool[pi + col], __float_as_int(fmaxf(acc[ti][nt][2] + bb0, 0.f)));
                    atomicMax(&s_pool[pi + col + 1], __float_as_int(fmaxf(acc[ti][nt][3] + bb1, 0.f)));
                }
            }
        }
    }
    __syncthreads();
    for (int j = tid; j < 3136; j += 256) {
        int img = j / 1568, rem = j - img * 1568;
        float v = __int_as_float(s_pool[j]);
        __nv_bfloat16 h, l;
        bf16split(v, h, l);
        int dst = (img0 + img) * 1568 + rem;
        g_a2h[dst] = h; g_a2l[dst] = l;
    }
}

// ---------------- conv3 (32->64) via bf16x3 tensor MMA + fused relu+pool(pad1) ----------------
#define C3_SMEM 182784
__global__ void __launch_bounds__(256, 1) k_conv3(const float* __restrict__ w3,
                                                  const float* __restrict__ b3) {
    extern __shared__ char smem[];
    __nv_bfloat16* s_inh = (__nv_bfloat16*)(smem);             // 4*4488 elems
    __nv_bfloat16* s_inl = (__nv_bfloat16*)(smem + 35904);
    __nv_bfloat16* s_wh  = (__nv_bfloat16*)(smem + 71808);     // 32*802
    __nv_bfloat16* s_wl  = (__nv_bfloat16*)(smem + 123136);
    int*           s_pool = (int*)(smem + 174464);             // 4*16*32
    float*         s_bias = (float*)(smem + 182656);

    const int img0 = blockIdx.x * 4;
    const int g = blockIdx.y;        // oc-group: 0 or 1
    const int tid = threadIdx.x;
    const int warp = tid >> 5;
    const int lane = tid & 31;
    const int gid = lane >> 2;
    const int tg  = lane & 3;
    const int kk  = tg * 2;

    uint32_t* zin = (uint32_t*)smem;
    for (int i = tid; i < 17952; i += 256) zin[i] = 0u;
    for (int i = tid; i < 2048; i += 256) s_pool[i] = 0;
    if (tid < 32) s_bias[tid] = b3[g * 32 + tid];
    const float* wg = w3 + g * 32 * 800;
    for (int i = tid; i < 25600; i += 256) {
        int ocl = i / 800, r = i - ocl * 800;
        int ic = r / 25, off = r - ic * 25;
        __nv_bfloat16 h, l;
        bf16split(wg[i], h, l);
        int d = ocl * 802 + off * 32 + ic;
        s_wh[d] = h; s_wl[d] = l;
    }
    __syncthreads();
    for (int i = tid; i < 6272; i += 256) {
        int img = i / 1568, rem = i - img * 1568;
        int p = rem / 32, ic = rem - p * 32;
        int y = p / 7, x = p - y * 7;
        int src = (img0 + img) * 1568 + rem;
        int d = img * 4488 + ((y + 2) * 12 + (x + 2)) * 34 + ic;
        s_inh[d] = g_a2h[src];
        s_inl[d] = g_a2l[src];
    }
    __syncthreads();

    int aoff0[2], aoff1[2];
#pragma unroll
    for (int ti = 0; ti < 2; ti++) {
        int t = warp + 8 * ti;
        int img = t >> 2, base = (t & 3) * 16;
        int p0 = base + gid; if (p0 > 48) p0 = 48;
        int p1 = base + gid + 8; if (p1 > 48) p1 = 48;
        int y0 = p0 / 7, x0 = p0 - y0 * 7;
        int y1 = p1 / 7, x1 = p1 - y1 * 7;
        aoff0[ti] = img * 4488 + (y0 * 12 + x0) * 34;
        aoff1[ti] = img * 4488 + (y1 * 12 + x1) * 34;
    }

    float acc[2][4][4];
#pragma unroll
    for (int ti = 0; ti < 2; ti++)
#pragma unroll
        for (int nt = 0; nt < 4; nt++)
#pragma unroll
            for (int j = 0; j < 4; j++) acc[ti][nt][j] = 0.f;

#pragma unroll 1
    for (int s = 0; s < 50; s++) {
        int off = s >> 1;
        int ich = (s & 1) * 16;
        int dy = off / 5, dx = off - dy * 5;
        int dbase = (dy * 12 + dx) * 34 + ich + kk;
        uint32_t bh0[4], bh1[4], bl0[4], bl1[4];
#pragma unroll
        for (int nt = 0; nt < 4; nt++) {
            int wr = (nt * 8 + gid) * 802 + off * 32 + ich + kk;
            bh0[nt] = lds_u32(s_wh, wr); bh1[nt] = lds_u32(s_wh, wr + 8);
            bl0[nt] = lds_u32(s_wl, wr); bl1[nt] = lds_u32(s_wl, wr + 8);
        }
#pragma unroll
        for (int ti = 0; ti < 2; ti++) {
            int o0 = aoff0[ti] + dbase;
            int o1 = aoff1[ti] + dbase;
            uint32_t ah0 = lds_u32(s_inh, o0), ah1 = lds_u32(s_inh, o1);
            uint32_t ah2 = lds_u32(s_inh, o0 + 8), ah3 = lds_u32(s_inh, o1 + 8);
            uint32_t al0 = lds_u32(s_inl, o0), al1 = lds_u32(s_inl, o1);
            uint32_t al2 = lds_u32(s_inl, o0 + 8), al3 = lds_u32(s_inl, o1 + 8);
#pragma unroll
            for (int nt = 0; nt < 4; nt++)
                mma_bf16(acc[ti][nt], ah0, ah1, ah2, ah3, bh0[nt], bh1[nt]);
#pragma unroll
            for (int nt = 0; nt < 4; nt++)
                mma_bf16(acc[ti][nt], ah0, ah1, ah2, ah3, bl0[nt], bl1[nt]);
#pragma unroll
            for (int nt = 0; nt < 4; nt++)
                mma_bf16(acc[ti][nt], al0, al1, al2, al3, bh0[nt], bh1[nt]);
        }
    }

#pragma unroll
    for (int ti = 0; ti < 2; ti++) {
        int t = warp + 8 * ti;
        int img = t >> 2, base = (t & 3) * 16;
        int p0 = base + gid, p1 = p0 + 8;
#pragma unroll
        for (int nt = 0; nt < 4; nt++) {
            int col = nt * 8 + kk;
            float bb0 = s_bias[col], bb1 = s_bias[col + 1];
            if (p0 < 49) {
                int y = p0 / 7, x = p0 - y * 7;
                int pi = img * 512 + (((y + 1) >> 1) * 4 + ((x + 1) >> 1)) * 32;
                atomicMax(&s_pool[pi + col], __float_as_int(fmaxf(acc[ti][nt][0] + bb0, 0.f)));
                atomicMax(&s_pool[pi + col + 1], __float_as_int(fmaxf(acc[ti][nt][1] + bb1, 0.f)));
            }
            if (p1 < 49) {
                int y = p1 / 7, x = p1 - y * 7;
                int pi = img * 512 + (((y + 1) >> 1) * 4 + ((x + 1) >> 1)) * 32;
                atomicMax(&s_pool[pi + col], __float_as_int(fmaxf(acc[ti][nt][2] + bb0, 0.f)));
                atomicMax(&s_pool[pi + col + 1], __float_as_int(fmaxf(acc[ti][nt][3] + bb1, 0.f)));
            }
        }
    }
    __syncthreads();
    // s_pool[img][pidx*32 + ocl] -> g_a3{h,l}[b][(g*32+ocl)*16 + pidx]
    for (int j = tid; j < 2048; j += 256) {
        int img = j >> 9, rem = j & 511;
        int pidx = rem >> 5, ocl = rem & 31;
        float v = __int_as_float(s_pool[j]);
        __nv_bfloat16 h, l;
        bf16split(v, h, l);
        int dst = (img0 + img) * 1024 + (g * 32 + ocl) * 16 + pidx;
        g_a3h[dst] = h; g_a3l[dst] = l;
    }
}

// ---------------- fc1 via bf16x3 tensor MMA: [8192,1024]@[256,1024]^T + bias, relu ----------------
// Block 128(M) x 128(N), 8 warps (4x2), warp tile m32n64. K staged 64/iter.
#define FC1_STRIDE 72
#define FC1_SMEM (4 * 128 * FC1_STRIDE * 2)   // 73728 bytes
__global__ void __launch_bounds__(256) k_fc1(const float* __restrict__ bias) {
    extern __shared__ char smem[];
    __nv_bfloat16* s_ah = (__nv_bfloat16*)smem;
    __nv_bfloat16* s_al = s_ah + 128 * FC1_STRIDE;
    __nv_bfloat16* s_bh = s_al + 128 * FC1_STRIDE;
    __nv_bfloat16* s_bl = s_bh + 128 * FC1_STRIDE;
    const int tid = threadIdx.x;
    const int warp = tid >> 5, lane = tid & 31;
    const int wm = warp >> 1, wn = warp & 1;
    const int m0 = blockIdx.y * 128, n0 = blockIdx.x * 128;
    const int gid = lane >> 2, tg = lane & 3;

    float acc[2][8][4];
#pragma unroll
    for (int mt = 0; mt < 2; mt++)
#pragma unroll
        for (int nt = 0; nt < 8; nt++)
#pragma unroll
            for (int j = 0; j < 4; j++) acc[mt][nt][j] = 0.f;

#pragma unroll 1
    for (int k0 = 0; k0 < 1024; k0 += 64) {
        __syncthreads();
        // load A,B tiles (bf16 already split in gmem): 2048 uint4 total
        for (int i = tid; i < 2048; i += 256) {
            int j = i & 1023;
            int row = j >> 3, koct = j & 7;
            int eoff = row * FC1_STRIDE + koct * 8;
            int gsrc = row * 1024 + k0 + koct * 8;
            if (i < 1024) {
                *(uint4*)(s_ah + eoff) = *(const uint4*)(g_a3h + (m0 * 1024) + gsrc);
                *(uint4*)(s_al + eoff) = *(const uint4*)(g_a3l + (m0 * 1024) + gsrc);
            } else {
                *(uint4*)(s_bh + eoff) = *(const uint4*)(g_fw1h + (n0 * 1024) + gsrc);
                *(uint4*)(s_bl + eoff) = *(const uint4*)(g_fw1l + (n0 * 1024) + gsrc);
            }
        }
        __syncthreads();
#pragma unroll
        for (int ks = 0; ks < 4; ks++) {
            int kb = ks * 16 + tg * 2;
            uint32_t ah[2][4], al[2][4];
#pragma unroll
            for (int mt = 0; mt < 2; mt++) {
                int base = (wm * 32 + mt * 16 + gid) * FC1_STRIDE + kb;
                ah[mt][0] = lds_u32(s_ah, base);
                ah[mt][1] = lds_u32(s_ah, base + 8 * FC1_STRIDE);
                ah[mt][2] = lds_u32(s_ah, base + 8);
                ah[mt][3] = lds_u32(s_ah, base + 8 * FC1_STRIDE + 8);
                al[mt][0] = lds_u32(s_al, base);
                al[mt][1] = lds_u32(s_al, base + 8 * FC1_STRIDE);
                al[mt][2] = lds_u32(s_al, base + 8);
                al[mt][3] = lds_u32(s_al, base + 8 * FC1_STRIDE + 8);
            }
            uint32_t bh[8][2], bl[8][2];
#pragma unroll
            for (int nt = 0; nt < 8; nt++) {
                int base = (wn * 64 + nt * 8 + gid) * FC1_STRIDE + kb;
                bh[nt][0] = lds_u32(s_bh, base); bh[nt][1] = lds_u32(s_bh, base + 8);
                bl[nt][0] = lds_u32(s_bl, base); bl[nt][1] = lds_u32(s_bl, base + 8);
            }
#pragma unroll
            for (int mt = 0; mt < 2; mt++) {
#pragma unroll
                for (int nt = 0; nt < 8; nt++)
                    mma_bf16(acc[mt][nt], ah[mt][0], ah[mt][1], ah[mt][2], ah[mt][3], bh[nt][0], bh[nt][1]);
#pragma unroll
                for (int nt = 0; nt < 8; nt++)
                    mma_bf16(acc[mt][nt], ah[mt][0], ah[mt][1], ah[mt][2], ah[mt][3], bl[nt][0], bl[nt][1]);
#pragma unroll
                for (int nt = 0; nt < 8; nt++)
                    mma_bf16(acc[mt][nt], al[mt][0], al[mt][1], al[mt][2], al[mt][3], bh[nt][0], bh[nt][1]);
            }
        }
    }
    // epilogue: bias + relu
#pragma unroll
    for (int mt = 0; mt < 2; mt++) {
        int r = m0 + wm * 32 + mt * 16 + gid;
#pragma unroll
        for (int nt = 0; nt < 8; nt++) {
            int c = n0 + wn * 64 + nt * 8 + tg * 2;
            float b0 = bias[c], b1 = bias[c + 1];
            g_a4[r * 256 + c]           = fmaxf(acc[mt][nt][0] + b0, 0.f);
            g_a4[r * 256 + c + 1]       = fmaxf(acc[mt][nt][1] + b1, 0.f);
            g_a4[(r + 8) * 256 + c]     = fmaxf(acc[mt][nt][2] + b0, 0.f);
            g_a4[(r + 8) * 256 + c + 1] = fmaxf(acc[mt][nt][3] + b1, 0.f);
        }
    }
}

// ---------------- fc2 + log_softmax ----------------
__global__ void __launch_bounds__(256) k_fc2(const float* __restrict__ W,
                                             const float* __restrict__ bias,
                                             float* __restrict__ out) {
    __shared__ float s_w[2560];
    __shared__ float s_b[10];
    const int tid = threadIdx.x;
    for (int i = tid; i < 2560; i += 256) s_w[i] = W[i];
    if (tid < 10) s_b[tid] = bias[tid];
    __syncthreads();

    const int warp = tid >> 5, lane = tid & 31;
    const int row = blockIdx.x * 8 + warp;
    float hv[8];
    const float* hp = g_a4 + row * 256 + lane;
#pragma unroll
    for (int j = 0; j < 8; j++) hv[j] = hp[j * 32];

    float acc[10];
#pragma unroll
    for (int o = 0; o < 10; o++) acc[o] = 0.f;
#pragma unroll
    for (int j = 0; j < 8; j++) {
#pragma unroll
        for (int o = 0; o < 10; o++)
            acc[o] += hv[j] * s_w[o * 256 + lane + j * 32];
    }
#pragma unroll
    for (int o = 0; o < 10; o++) {
#pragma unroll
        for (int off = 16; off > 0; off >>= 1)
            acc[o] += __shfl_xor_sync(0xffffffffu, acc[o], off);
    }
    if (lane == 0) {
        float l[10], m = -1e30f;
#pragma unroll
        for (int o = 0; o < 10; o++) { l[o] = acc[o] + s_b[o]; m = fmaxf(m, l[o]); }
        float s = 0.f;
#pragma unroll
        for (int o = 0; o < 10; o++) s += expf(l[o] - m);
        float ls = logf(s);
        float* op = out + row * 10;
#pragma unroll
        for (int o = 0; o < 10; o++) op[o] = l[o] - m - ls;
    }
}

extern "C" void kernel_launch(void* const* d_in, const int* in_sizes, int n_in,
                              void* d_out, int out_size) {
    const float* x   = (const float*)d_in[0];
    const float* w1  = (const float*)d_in[1];
    const float* b1  = (const float*)d_in[2];
    const float* w2  = (const float*)d_in[3];
    const float* b2  = (const float*)d_in[4];
    const float* w3  = (const float*)d_in[5];
    const float* b3  = (const float*)d_in[6];
    const float* fw1 = (const float*)d_in[7];
    const float* fb1 = (const float*)d_in[8];
    const float* fw2 = (const float*)d_in[9];
    const float* fb2 = (const float*)d_in[10];
    float* out = (float*)d_out;

    cudaFuncSetAttribute(k_conv2, cudaFuncAttributeMaxDynamicSharedMemorySize, C2_SMEM);
    cudaFuncSetAttribute(k_conv3, cudaFuncAttributeMaxDynamicSharedMemorySize, C3_SMEM);
    cudaFuncSetAttribute(k_fc1,   cudaFuncAttributeMaxDynamicSharedMemorySize, FC1_SMEM);

    k_prep<<<1024, 256>>>(fw1);
    k_conv1<<<BATCH, 224>>>(x, w1, b1);
    k_conv2<<<BATCH / 2, 256, C2_SMEM>>>(w2, b2);
    k_conv3<<<dim3(BATCH / 4, 2), 256, C3_SMEM>>>(w3, b3);
    k_fc1<<<dim3(2, BATCH / 128), 256, FC1_SMEM>>>(fb1);
    k_fc2<<<BATCH / 8, 256>>>(fw2, fb2, out);
}